// round 4
// baseline (speedup 1.0000x reference)
#include <cuda_runtime.h>

// Problem constants: B=8192, T=64, D=512
#define BB 8192
#define TT 64
#define DD 512
#define NW 4            // warps per CTA (128 threads)

__device__ __forceinline__ float warp_reduce_sum(float v) {
    #pragma unroll
    for (int off = 16; off > 0; off >>= 1)
        v += __shfl_xor_sync(0xFFFFFFFFu, v, off);
    return v;
}

__global__ __launch_bounds__(128, 16)
void sdpa_decode_kernel(const float* __restrict__ q,
                        const float* __restrict__ k,
                        const float* __restrict__ v,
                        const int*   __restrict__ pad_mask,
                        float* __restrict__ out,       // [B, D]
                        float* __restrict__ attn_out)  // [B, T]
{
    const int b    = blockIdx.x;
    const int tid  = threadIdx.x;
    const int warp = tid >> 5;
    const int lane = tid & 31;

    const float INV_TEMP  = 0.04419417382415922f;   // 1/sqrt(512)
    const float MASK_FILL = -1000.0f;

    __shared__ float4 qs[DD / 4];     // q row: 128 float4
    __shared__ float  s_logit[TT];
    __shared__ int    s_mask[TT];
    __shared__ float  s_p[TT];        // probabilities in compacted order
    __shared__ int    s_t[TT];        // active t indices (compacted)
    __shared__ int    s_na;           // active count

    // ---- load q[b] (1 float4/thread) and pad_mask[b] ----
    qs[tid] = reinterpret_cast<const float4*>(q + (size_t)b * DD)[tid];
    if (tid < TT) s_mask[tid] = pad_mask[(size_t)b * TT + tid];
    __syncthreads();

    // ---- build compacted active-row list BEFORE QK (mask-only ballot) ----
    if (warp == 0) {
        int m0 = s_mask[lane];
        int m1 = s_mask[lane + 32];
        unsigned b0 = __ballot_sync(0xFFFFFFFFu, m0 == 0);
        unsigned b1 = __ballot_sync(0xFFFFFFFFu, m1 == 0);
        int n0 = __popc(b0);
        unsigned lt = (1u << lane) - 1u;
        if (!m0) s_t[__popc(b0 & lt)]      = lane;
        if (!m1) s_t[n0 + __popc(b1 & lt)] = lane + 32;
        if (lane == 0) s_na = n0 + __popc(b1);
    }
    __syncthreads();
    const int na = s_na;

    // ---- QK^T over active rows, balanced across warps, 2 rows per pass ----
    const float4* kbase = reinterpret_cast<const float4*>(k + (size_t)b * TT * DD);
    {
        int i = warp;
        for (; i + NW < na; i += 2 * NW) {
            const int ta = s_t[i];
            const int tb = s_t[i + NW];
            const float4* ka = kbase + (size_t)ta * (DD / 4);
            const float4* kb = kbase + (size_t)tb * (DD / 4);
            float pa = 0.0f, pb = 0.0f;
            #pragma unroll
            for (int j = 0; j < 4; j++) {
                const int idx = lane + j * 32;
                float4 av = ka[idx];
                float4 bv = kb[idx];
                float4 qv = qs[idx];
                pa += av.x * qv.x + av.y * qv.y + av.z * qv.z + av.w * qv.w;
                pb += bv.x * qv.x + bv.y * qv.y + bv.z * qv.z + bv.w * qv.w;
            }
            pa = warp_reduce_sum(pa);
            pb = warp_reduce_sum(pb);
            if (lane == 0) { s_logit[ta] = pa; s_logit[tb] = pb; }
        }
        if (i < na) {
            const int ta = s_t[i];
            const float4* ka = kbase + (size_t)ta * (DD / 4);
            float pa = 0.0f;
            #pragma unroll
            for (int j = 0; j < 4; j++) {
                const int idx = lane + j * 32;
                float4 av = ka[idx];
                float4 qv = qs[idx];
                pa += av.x * qv.x + av.y * qv.y + av.z * qv.z + av.w * qv.w;
            }
            pa = warp_reduce_sum(pa);
            if (lane == 0) s_logit[ta] = pa;
        }
    }
    __syncthreads();

    // ---- masked softmax (warp 0, 2 values/lane); write attn; fill s_p ----
    if (warp == 0) {
        int m0 = s_mask[lane];
        int m1 = s_mask[lane + 32];
        float v0 = m0 ? MASK_FILL : s_logit[lane]      * INV_TEMP;
        float v1 = m1 ? MASK_FILL : s_logit[lane + 32] * INV_TEMP;

        float m = fmaxf(v0, v1);
        #pragma unroll
        for (int off = 16; off > 0; off >>= 1)
            m = fmaxf(m, __shfl_xor_sync(0xFFFFFFFFu, m, off));

        float e0 = __expf(v0 - m);   // exact 0 for masked rows (matches reference)
        float e1 = __expf(v1 - m);
        float ssum = warp_reduce_sum(e0 + e1);
        float inv = 1.0f / ssum;
        float p0 = e0 * inv;
        float p1 = e1 * inv;

        attn_out[(size_t)b * TT + lane]      = p0;
        attn_out[(size_t)b * TT + lane + 32] = p1;

        // probabilities into compacted slots (same ballot math as list build)
        unsigned b0 = __ballot_sync(0xFFFFFFFFu, m0 == 0);
        unsigned b1 = __ballot_sync(0xFFFFFFFFu, m1 == 0);
        int n0 = __popc(b0);
        unsigned lt = (1u << lane) - 1u;
        if (!m0) s_p[__popc(b0 & lt)]      = p0;
        if (!m1) s_p[n0 + __popc(b1 & lt)] = p1;

        // all-masked edge case: reference gives uniform 1/64 over ALL rows
        if (n0 + __popc(b1) == 0) {
            s_t[lane]      = lane;      s_p[lane]      = p0;  // p0 == 1/64 here
            s_t[lane + 32] = lane + 32; s_p[lane + 32] = p1;
            if (lane == 0) s_na = TT;
        }
    }
    __syncthreads();

    // ---- P·V over active rows: one float4 per thread per row, unroll x4 ----
    const float4* vbase = reinterpret_cast<const float4*>(v + (size_t)b * TT * DD);
    const int nact = s_na;
    float4 acc = make_float4(0.0f, 0.0f, 0.0f, 0.0f);

    int j = 0;
    for (; j + 4 <= nact; j += 4) {
        float pa = s_p[j],     pb = s_p[j + 1], pc = s_p[j + 2], pd = s_p[j + 3];
        int   ta = s_t[j],     tb = s_t[j + 1], tc = s_t[j + 2], td = s_t[j + 3];
        float4 va = vbase[(size_t)ta * (DD / 4) + tid];
        float4 vb = vbase[(size_t)tb * (DD / 4) + tid];
        float4 vc = vbase[(size_t)tc * (DD / 4) + tid];
        float4 vd = vbase[(size_t)td * (DD / 4) + tid];
        acc.x += pa * va.x; acc.y += pa * va.y; acc.z += pa * va.z; acc.w += pa * va.w;
        acc.x += pb * vb.x; acc.y += pb * vb.y; acc.z += pb * vb.z; acc.w += pb * vb.w;
        acc.x += pc * vc.x; acc.y += pc * vc.y; acc.z += pc * vc.z; acc.w += pc * vc.w;
        acc.x += pd * vd.x; acc.y += pd * vd.y; acc.z += pd * vd.z; acc.w += pd * vd.w;
    }
    for (; j < nact; j++) {
        float  p  = s_p[j];
        float4 vv = vbase[(size_t)s_t[j] * (DD / 4) + tid];
        acc.x += p * vv.x; acc.y += p * vv.y; acc.z += p * vv.z; acc.w += p * vv.w;
    }
    reinterpret_cast<float4*>(out + (size_t)b * DD)[tid] = acc;
}

extern "C" void kernel_launch(void* const* d_in, const int* in_sizes, int n_in,
                              void* d_out, int out_size) {
    const float* q        = (const float*)d_in[0];   // [B, D]
    const float* k        = (const float*)d_in[1];   // [B, T, D]
    const float* v        = (const float*)d_in[2];   // [B, T, D]
    const int*   pad_mask = (const int*)  d_in[3];   // [B, T]

    float* out      = (float*)d_out;                   // [B,1,D]
    float* attn_out = (float*)d_out + (size_t)BB * DD; // [B,1,T]

    sdpa_decode_kernel<<<BB, 128>>>(q, k, v, pad_mask, out, attn_out);
}